// round 4
// baseline (speedup 1.0000x reference)
#include <cuda_runtime.h>
#include <cstdint>

// LightGCN: out = 0.25*(X + h1 + h2 + h3), h_{k+1} = A h_k (weighted scatter-sum)
// Pull-based: build dst-sorted CSR per launch, then 3 atomic-free gather layers.
// R4: pull path reverted to the R2 (162us) form; parallel tops-scan kept.

#define N_NODES 100000
#define D_FEAT  64
#define MAX_E   1600000
#define SCAN_BS 1024
#define N_SCAN_BLOCKS ((N_NODES + SCAN_BS - 1) / SCAN_BS)   // 98

// Static scratch (no allocation allowed).
__device__ float g_bufA[(size_t)N_NODES * D_FEAT];
__device__ float g_bufB[(size_t)N_NODES * D_FEAT];
__device__ int   g_deg[N_NODES];
__device__ int   g_incl[N_NODES];
__device__ int   g_blockSums[N_SCAN_BLOCKS];
__device__ int   g_blockOff[N_SCAN_BLOCKS];
__device__ int   g_off[N_NODES + 1];
__device__ int   g_cursor[N_NODES];
__device__ int   g_ssrc[MAX_E];
__device__ float g_sew[MAX_E];

// ---------------- CSR construction ----------------

__global__ void k_zero_deg(int n4) {
    int i = blockIdx.x * blockDim.x + threadIdx.x;
    if (i < n4) reinterpret_cast<int4*>(g_deg)[i] = make_int4(0, 0, 0, 0);
}

__global__ void k_hist(const int* __restrict__ dst, int nE) {
    int e = blockIdx.x * blockDim.x + threadIdx.x;
    if (e < nE) atomicAdd(&g_deg[dst[e]], 1);
}

// Per-block inclusive scan (Hillis-Steele) + block sums.
__global__ void k_scan_block(int n) {
    __shared__ int sh[SCAN_BS];
    int t = threadIdx.x;
    int i = blockIdx.x * SCAN_BS + t;
    int v = (i < n) ? g_deg[i] : 0;
    sh[t] = v;
    __syncthreads();
    for (int d = 1; d < SCAN_BS; d <<= 1) {
        int x = (t >= d) ? sh[t - d] : 0;
        __syncthreads();
        sh[t] += x;
        __syncthreads();
    }
    if (i < n) g_incl[i] = sh[t];
    if (t == SCAN_BS - 1) g_blockSums[blockIdx.x] = sh[t];
}

// Parallel exclusive scan of the 98 block sums (single 128-thread block).
__global__ void k_scan_tops() {
    __shared__ int sh[128];
    int t = threadIdx.x;
    int v = (t < N_SCAN_BLOCKS) ? g_blockSums[t] : 0;
    sh[t] = v;
    __syncthreads();
    for (int d = 1; d < 128; d <<= 1) {
        int x = (t >= d) ? sh[t - d] : 0;
        __syncthreads();
        sh[t] += x;
        __syncthreads();
    }
    if (t < N_SCAN_BLOCKS) g_blockOff[t] = sh[t] - v;   // exclusive
}

__global__ void k_finalize_off(int n, int nE) {
    int i = blockIdx.x * blockDim.x + threadIdx.x;
    if (i >= n) return;
    int excl = g_incl[i] + g_blockOff[i >> 10] - g_deg[i];
    g_off[i] = excl;
    g_cursor[i] = excl;
    if (i == n - 1) g_off[n] = nE;
}

__global__ void k_scatter(const int* __restrict__ src,
                          const int* __restrict__ dst,
                          const float* __restrict__ ew, int nE) {
    int e = blockIdx.x * blockDim.x + threadIdx.x;
    if (e >= nE) return;
    int d = dst[e];
    int pos = atomicAdd(&g_cursor[d], 1);
    g_ssrc[pos] = src[e];
    g_sew[pos]  = ew[e];
}

// ---------------- Pull SpMM (R2 form) ----------------
// One warp per dst node. Lanes 0-15 process even edges, lanes 16-31 odd edges.
// Each lane owns one float4 column chunk (16 x 16B = 256B row).

__device__ __forceinline__ float4 warp_node_reduce(const float* __restrict__ Xin,
                                                   int node, int c, int half) {
    int begin = g_off[node], end = g_off[node + 1];
    float4 acc = make_float4(0.f, 0.f, 0.f, 0.f);
    for (int e = begin + half; e < end; e += 2) {
        int   s = g_ssrc[e];
        float w = g_sew[e];
        float4 v = *reinterpret_cast<const float4*>(Xin + (size_t)s * D_FEAT + (c << 2));
        acc.x += w * v.x; acc.y += w * v.y; acc.z += w * v.z; acc.w += w * v.w;
    }
    // combine the two edge-halves (same columns in both halves)
    acc.x += __shfl_xor_sync(0xffffffff, acc.x, 16);
    acc.y += __shfl_xor_sync(0xffffffff, acc.y, 16);
    acc.z += __shfl_xor_sync(0xffffffff, acc.z, 16);
    acc.w += __shfl_xor_sync(0xffffffff, acc.w, 16);
    return acc;
}

__global__ void k_pull(const float* __restrict__ Xin,
                       float* __restrict__ Xout) {
    int gwarp = (blockIdx.x * blockDim.x + threadIdx.x) >> 5;
    if (gwarp >= N_NODES) return;
    int lane = threadIdx.x & 31;
    int half = lane >> 4;
    int c    = lane & 15;
    float4 acc = warp_node_reduce(Xin, gwarp, c, half);
    if (half == 0)
        *reinterpret_cast<float4*>(Xout + (size_t)gwarp * D_FEAT + (c << 2)) = acc;
}

// Final layer fused with the mean: out = 0.25*(X + h1 + h2 + h3)
__global__ void k_pull_final(const float* __restrict__ Xin,   // h2
                             const float* __restrict__ X,
                             const float* __restrict__ h1,
                             float* __restrict__ out) {
    int gwarp = (blockIdx.x * blockDim.x + threadIdx.x) >> 5;
    if (gwarp >= N_NODES) return;
    int lane = threadIdx.x & 31;
    int half = lane >> 4;
    int c    = lane & 15;
    float4 acc = warp_node_reduce(Xin, gwarp, c, half);   // h3 chunk
    if (half == 0) {
        size_t idx = (size_t)gwarp * D_FEAT + (c << 2);
        float4 x0 = *reinterpret_cast<const float4*>(X   + idx);
        float4 x1 = *reinterpret_cast<const float4*>(h1  + idx);
        float4 x2 = *reinterpret_cast<const float4*>(Xin + idx);
        float4 o;
        o.x = 0.25f * (x0.x + x1.x + x2.x + acc.x);
        o.y = 0.25f * (x0.y + x1.y + x2.y + acc.y);
        o.z = 0.25f * (x0.z + x1.z + x2.z + acc.z);
        o.w = 0.25f * (x0.w + x1.w + x2.w + acc.w);
        *reinterpret_cast<float4*>(out + idx) = o;
    }
}

extern "C" void kernel_launch(void* const* d_in, const int* in_sizes, int n_in,
                              void* d_out, int out_size) {
    const float* X   = (const float*)d_in[0];
    const int*   src = (const int*)  d_in[1];
    const int*   dst = (const int*)  d_in[2];
    const float* ew  = (const float*)d_in[3];
    float* out = (float*)d_out;

    const int nE = in_sizes[1];

    float* bufA = nullptr;
    float* bufB = nullptr;
    cudaGetSymbolAddress((void**)&bufA, g_bufA);
    cudaGetSymbolAddress((void**)&bufB, g_bufB);

    const int TB = 256;
    const int gridNode = (N_NODES + TB - 1) / TB;
    const int gridZ    = (N_NODES / 4 + TB - 1) / TB;
    const int gridE    = (nE + TB - 1) / TB;
    const int gridPull = (N_NODES * 32 + TB - 1) / TB;   // warp per node

    // --- build dst-sorted CSR ---
    k_zero_deg<<<gridZ, TB>>>(N_NODES / 4);
    k_hist<<<gridE, TB>>>(dst, nE);
    k_scan_block<<<N_SCAN_BLOCKS, SCAN_BS>>>(N_NODES);
    k_scan_tops<<<1, 128>>>();
    k_finalize_off<<<gridNode, TB>>>(N_NODES, nE);
    k_scatter<<<gridE, TB>>>(src, dst, ew, nE);

    // --- 3 pull layers, final fused with the mean ---
    k_pull<<<gridPull, TB>>>(X, bufA);                    // h1
    k_pull<<<gridPull, TB>>>(bufA, bufB);                 // h2
    k_pull_final<<<gridPull, TB>>>(bufB, X, bufA, out);   // h3 + mean
}

// round 5
// speedup vs baseline: 1.4061x; 1.4061x over previous
#include <cuda_runtime.h>
#include <cuda_fp16.h>
#include <cstdint>

// LightGCN: out = 0.25*(X + h1 + h2 + h3), h_{k+1} = A h_k (weighted scatter-sum)
// Pull-based CSR (atomic-free feature path). R5: fp16 gather operands (halves
// L2 gather traffic); accumulation and the final mean stay fp32.

#define N_NODES 100000
#define D_FEAT  64
#define MAX_E   1600000
#define SCAN_BS 1024
#define N_SCAN_BLOCKS ((N_NODES + SCAN_BS - 1) / SCAN_BS)   // 98

// Static scratch (no allocation allowed).
__device__ float  g_bufA[(size_t)N_NODES * D_FEAT];   // h1 (fp32, exact for mean)
__device__ float  g_bufB[(size_t)N_NODES * D_FEAT];   // h2 (fp32, exact for mean)
__device__ __half g_hA[(size_t)N_NODES * D_FEAT];     // fp16 gather copies
__device__ __half g_hB[(size_t)N_NODES * D_FEAT];
__device__ int    g_deg[N_NODES];
__device__ int    g_incl[N_NODES];
__device__ int    g_blockSums[N_SCAN_BLOCKS];
__device__ int    g_blockOff[N_SCAN_BLOCKS];
__device__ int    g_off[N_NODES + 1];
__device__ int    g_cursor[N_NODES];
__device__ int    g_ssrc[MAX_E];
__device__ float  g_sew[MAX_E];

// ---------------- CSR construction ----------------

__global__ void k_zero_deg(int n4) {
    int i = blockIdx.x * blockDim.x + threadIdx.x;
    if (i < n4) reinterpret_cast<int4*>(g_deg)[i] = make_int4(0, 0, 0, 0);
}

__global__ void k_hist(const int* __restrict__ dst, int nE) {
    int e = blockIdx.x * blockDim.x + threadIdx.x;
    if (e < nE) atomicAdd(&g_deg[dst[e]], 1);
}

__global__ void k_scan_block(int n) {
    __shared__ int sh[SCAN_BS];
    int t = threadIdx.x;
    int i = blockIdx.x * SCAN_BS + t;
    int v = (i < n) ? g_deg[i] : 0;
    sh[t] = v;
    __syncthreads();
    for (int d = 1; d < SCAN_BS; d <<= 1) {
        int x = (t >= d) ? sh[t - d] : 0;
        __syncthreads();
        sh[t] += x;
        __syncthreads();
    }
    if (i < n) g_incl[i] = sh[t];
    if (t == SCAN_BS - 1) g_blockSums[blockIdx.x] = sh[t];
}

__global__ void k_scan_tops() {
    __shared__ int sh[128];
    int t = threadIdx.x;
    int v = (t < N_SCAN_BLOCKS) ? g_blockSums[t] : 0;
    sh[t] = v;
    __syncthreads();
    for (int d = 1; d < 128; d <<= 1) {
        int x = (t >= d) ? sh[t - d] : 0;
        __syncthreads();
        sh[t] += x;
        __syncthreads();
    }
    if (t < N_SCAN_BLOCKS) g_blockOff[t] = sh[t] - v;   // exclusive
}

__global__ void k_finalize_off(int n, int nE) {
    int i = blockIdx.x * blockDim.x + threadIdx.x;
    if (i >= n) return;
    int excl = g_incl[i] + g_blockOff[i >> 10] - g_deg[i];
    g_off[i] = excl;
    g_cursor[i] = excl;
    if (i == n - 1) g_off[n] = nE;
}

__global__ void k_scatter(const int* __restrict__ src,
                          const int* __restrict__ dst,
                          const float* __restrict__ ew, int nE) {
    int e = blockIdx.x * blockDim.x + threadIdx.x;
    if (e >= nE) return;
    int d = dst[e];
    int pos = atomicAdd(&g_cursor[d], 1);
    g_ssrc[pos] = src[e];
    g_sew[pos]  = ew[e];
}

// ---------------- fp32 -> fp16 convert (X) ----------------
// Each thread converts 8 floats -> 8 halfs (16B store).
__global__ void k_x2h(const float* __restrict__ X, __half* __restrict__ out, int n8) {
    int i = blockIdx.x * blockDim.x + threadIdx.x;
    if (i >= n8) return;
    const float4* x4 = reinterpret_cast<const float4*>(X);
    float4 a = x4[2 * i];
    float4 b = x4[2 * i + 1];
    __half2 h0 = __floats2half2_rn(a.x, a.y);
    __half2 h1 = __floats2half2_rn(a.z, a.w);
    __half2 h2 = __floats2half2_rn(b.x, b.y);
    __half2 h3 = __floats2half2_rn(b.z, b.w);
    uint4 r;
    r.x = *reinterpret_cast<unsigned*>(&h0);
    r.y = *reinterpret_cast<unsigned*>(&h1);
    r.z = *reinterpret_cast<unsigned*>(&h2);
    r.w = *reinterpret_cast<unsigned*>(&h3);
    reinterpret_cast<uint4*>(out)[i] = r;
}

// ---------------- Pull SpMM (fp16 gathers, fp32 accumulate) ----------------
// One warp per dst node. Lanes 0-15 = even edges, lanes 16-31 = odd edges.
// Lane c (0..15) owns features [4c, 4c+4) = 8 bytes of the fp16 row
// (16 lanes x 8B = 128B = one full row, one L2 line).

__device__ __forceinline__ float4 warp_node_reduce_h(const __half* __restrict__ Hin,
                                                     int node, int c, int half) {
    int begin = g_off[node], end = g_off[node + 1];
    float4 acc = make_float4(0.f, 0.f, 0.f, 0.f);
    for (int e = begin + half; e < end; e += 2) {
        int   s = g_ssrc[e];
        float w = g_sew[e];
        uint2 u = reinterpret_cast<const uint2*>(Hin + (size_t)s * D_FEAT)[c];
        float2 fa = __half22float2(*reinterpret_cast<__half2*>(&u.x));
        float2 fb = __half22float2(*reinterpret_cast<__half2*>(&u.y));
        acc.x += w * fa.x; acc.y += w * fa.y; acc.z += w * fb.x; acc.w += w * fb.y;
    }
    acc.x += __shfl_xor_sync(0xffffffff, acc.x, 16);
    acc.y += __shfl_xor_sync(0xffffffff, acc.y, 16);
    acc.z += __shfl_xor_sync(0xffffffff, acc.z, 16);
    acc.w += __shfl_xor_sync(0xffffffff, acc.w, 16);
    return acc;
}

// Writes fp32 (exact, for the final mean) and fp16 (for next layer's gathers).
__global__ void k_pull_h(const __half* __restrict__ Hin,
                         float* __restrict__ Fout,
                         __half* __restrict__ Hout) {
    int gwarp = (blockIdx.x * blockDim.x + threadIdx.x) >> 5;
    if (gwarp >= N_NODES) return;
    int lane = threadIdx.x & 31;
    int half = lane >> 4;
    int c    = lane & 15;
    float4 acc = warp_node_reduce_h(Hin, gwarp, c, half);
    if (half == 0) {
        *reinterpret_cast<float4*>(Fout + (size_t)gwarp * D_FEAT + (c << 2)) = acc;
        __half2 h0 = __floats2half2_rn(acc.x, acc.y);
        __half2 h1 = __floats2half2_rn(acc.z, acc.w);
        uint2 u;
        u.x = *reinterpret_cast<unsigned*>(&h0);
        u.y = *reinterpret_cast<unsigned*>(&h1);
        reinterpret_cast<uint2*>(Hout + (size_t)gwarp * D_FEAT)[c] = u;
    }
}

// Final layer fused with the mean: out = 0.25*(X + h1 + h2 + h3)
__global__ void k_pull_final_h(const __half* __restrict__ Hin,   // h2 (fp16)
                               const float* __restrict__ X,
                               const float* __restrict__ h1,
                               const float* __restrict__ h2,
                               float* __restrict__ out) {
    int gwarp = (blockIdx.x * blockDim.x + threadIdx.x) >> 5;
    if (gwarp >= N_NODES) return;
    int lane = threadIdx.x & 31;
    int half = lane >> 4;
    int c    = lane & 15;
    float4 acc = warp_node_reduce_h(Hin, gwarp, c, half);   // h3 chunk
    if (half == 0) {
        size_t idx = (size_t)gwarp * D_FEAT + (c << 2);
        float4 x0 = *reinterpret_cast<const float4*>(X  + idx);
        float4 x1 = *reinterpret_cast<const float4*>(h1 + idx);
        float4 x2 = *reinterpret_cast<const float4*>(h2 + idx);
        float4 o;
        o.x = 0.25f * (x0.x + x1.x + x2.x + acc.x);
        o.y = 0.25f * (x0.y + x1.y + x2.y + acc.y);
        o.z = 0.25f * (x0.z + x1.z + x2.z + acc.z);
        o.w = 0.25f * (x0.w + x1.w + x2.w + acc.w);
        *reinterpret_cast<float4*>(out + idx) = o;
    }
}

extern "C" void kernel_launch(void* const* d_in, const int* in_sizes, int n_in,
                              void* d_out, int out_size) {
    const float* X   = (const float*)d_in[0];
    const int*   src = (const int*)  d_in[1];
    const int*   dst = (const int*)  d_in[2];
    const float* ew  = (const float*)d_in[3];
    float* out = (float*)d_out;

    const int nE = in_sizes[1];

    float* bufA = nullptr;
    float* bufB = nullptr;
    __half* hA = nullptr;
    __half* hB = nullptr;
    cudaGetSymbolAddress((void**)&bufA, g_bufA);
    cudaGetSymbolAddress((void**)&bufB, g_bufB);
    cudaGetSymbolAddress((void**)&hA, g_hA);
    cudaGetSymbolAddress((void**)&hB, g_hB);

    const int TB = 256;
    const int gridNode = (N_NODES + TB - 1) / TB;
    const int gridZ    = (N_NODES / 4 + TB - 1) / TB;
    const int gridE    = (nE + TB - 1) / TB;
    const int gridPull = (N_NODES * 32 + TB - 1) / TB;   // warp per node
    const int n8       = N_NODES * D_FEAT / 8;
    const int gridC    = (n8 + TB - 1) / TB;

    // --- convert X to fp16 (gather copy) ---
    k_x2h<<<gridC, TB>>>(X, hA, n8);

    // --- build dst-sorted CSR ---
    k_zero_deg<<<gridZ, TB>>>(N_NODES / 4);
    k_hist<<<gridE, TB>>>(dst, nE);
    k_scan_block<<<N_SCAN_BLOCKS, SCAN_BS>>>(N_NODES);
    k_scan_tops<<<1, 128>>>();
    k_finalize_off<<<gridNode, TB>>>(N_NODES, nE);
    k_scatter<<<gridE, TB>>>(src, dst, ew, nE);

    // --- 3 pull layers (fp16 gathers, fp32 accumulation + mean) ---
    k_pull_h<<<gridPull, TB>>>(hA, bufA, hB);                    // h1
    k_pull_h<<<gridPull, TB>>>(hB, bufB, hA);                    // h2
    k_pull_final_h<<<gridPull, TB>>>(hA, X, bufA, bufB, out);    // h3 + mean
}

// round 6
// speedup vs baseline: 1.5056x; 1.0708x over previous
#include <cuda_runtime.h>
#include <cuda_fp16.h>
#include <cstdint>

// LightGCN: out = 0.25*(X + h1 + h2 + h3), h_{k+1} = A h_k
// Pull-based CSR, fp16 gather operands / fp32 accumulation.
// R6: launch-count compression (10 -> 7 kernels), packed (src,ew) edge payload.

#define N_NODES 100000
#define D_FEAT  64
#define MAX_E   1600000
#define SCAN_BS 1024
#define N_SCAN_BLOCKS ((N_NODES + SCAN_BS - 1) / SCAN_BS)   // 98

// Static scratch (no allocation allowed). All state is self-restoring across
// graph replays: deg is re-zeroed inside k_scan_block after being consumed.
__device__ float  g_bufA[(size_t)N_NODES * D_FEAT];   // h1 (fp32, exact for mean)
__device__ float  g_bufB[(size_t)N_NODES * D_FEAT];   // h2 (fp32, exact for mean)
__device__ __half g_hA[(size_t)N_NODES * D_FEAT];     // fp16 gather copies
__device__ __half g_hB[(size_t)N_NODES * D_FEAT];
__device__ int    g_deg[N_NODES];                     // zero-init; left zeroed each call
__device__ int    g_exloc[N_NODES];                   // block-local exclusive prefix
__device__ int    g_blockSums[N_SCAN_BLOCKS];
__device__ int    g_off[N_NODES + 1];
__device__ int    g_cursor[N_NODES];
__device__ int2   g_sedge[MAX_E];                     // packed (src, ew), dst-sorted

// ---- prep: fp32->fp16 convert of X, fused with the dst histogram ----
__global__ void k_prep(const float* __restrict__ X, __half* __restrict__ hX,
                       const int* __restrict__ dst, int n8, int nE) {
    int i = blockIdx.x * blockDim.x + threadIdx.x;
    if (i < n8) {
        const float4* x4 = reinterpret_cast<const float4*>(X);
        float4 a = x4[2 * i];
        float4 b = x4[2 * i + 1];
        __half2 h0 = __floats2half2_rn(a.x, a.y);
        __half2 h1 = __floats2half2_rn(a.z, a.w);
        __half2 h2 = __floats2half2_rn(b.x, b.y);
        __half2 h3 = __floats2half2_rn(b.z, b.w);
        uint4 r;
        r.x = *reinterpret_cast<unsigned*>(&h0);
        r.y = *reinterpret_cast<unsigned*>(&h1);
        r.z = *reinterpret_cast<unsigned*>(&h2);
        r.w = *reinterpret_cast<unsigned*>(&h3);
        reinterpret_cast<uint4*>(hX)[i] = r;
    }
    if (i < nE) atomicAdd(&g_deg[dst[i]], 1);
}

// ---- per-block scan: writes block-local EXCLUSIVE prefix + block sums,
//      then zeroes deg (restores state for the next graph replay) ----
__global__ void k_scan_block(int n) {
    __shared__ int sh[SCAN_BS];
    int t = threadIdx.x;
    int i = blockIdx.x * SCAN_BS + t;
    int v = (i < n) ? g_deg[i] : 0;
    sh[t] = v;
    __syncthreads();
    for (int d = 1; d < SCAN_BS; d <<= 1) {
        int x = (t >= d) ? sh[t - d] : 0;
        __syncthreads();
        sh[t] += x;
        __syncthreads();
    }
    if (i < n) {
        g_exloc[i] = sh[t] - v;   // exclusive within block
        g_deg[i] = 0;             // self-restore for next replay
    }
    if (t == SCAN_BS - 1) g_blockSums[blockIdx.x] = sh[t];
}

// ---- finalize: each 256-thread block recomputes its chunk's global base
//      from the 98 block sums (L2-hot), writes off + cursor ----
__global__ void k_finalize(int n, int nE) {
    __shared__ int s_base;
    int chunk = blockIdx.x >> 2;   // 4 blocks of 256 per 1024-wide scan chunk
    if (threadIdx.x < 32) {
        int acc = 0;
        for (int j = (int)threadIdx.x; j < chunk; j += 32) acc += g_blockSums[j];
        #pragma unroll
        for (int o = 16; o; o >>= 1) acc += __shfl_down_sync(0xffffffffu, acc, o);
        if (threadIdx.x == 0) s_base = acc;
    }
    __syncthreads();
    int i = blockIdx.x * 256 + threadIdx.x;
    if (i >= n) return;
    int excl = g_exloc[i] + s_base;
    g_off[i] = excl;
    g_cursor[i] = excl;
    if (i == n - 1) g_off[n] = nE;
}

__global__ void k_scatter(const int* __restrict__ src,
                          const int* __restrict__ dst,
                          const float* __restrict__ ew, int nE) {
    int e = blockIdx.x * blockDim.x + threadIdx.x;
    if (e >= nE) return;
    int d = dst[e];
    int pos = atomicAdd(&g_cursor[d], 1);
    g_sedge[pos] = make_int2(src[e], __float_as_int(ew[e]));
}

// ---------------- Pull SpMM (fp16 gathers, fp32 accumulate) ----------------
// One warp per dst node. Lanes 0-15 = even edges, lanes 16-31 = odd edges.
// Lane c (0..15) owns features [4c, 4c+4): 16 lanes x 8B = the full 128B row.

__device__ __forceinline__ float4 warp_node_reduce_h(const __half* __restrict__ Hin,
                                                     int node, int c, int half) {
    int begin = g_off[node], end = g_off[node + 1];
    float4 acc = make_float4(0.f, 0.f, 0.f, 0.f);
    for (int e = begin + half; e < end; e += 2) {
        int2  p = g_sedge[e];
        float w = __int_as_float(p.y);
        uint2 u = reinterpret_cast<const uint2*>(Hin + (size_t)p.x * D_FEAT)[c];
        float2 fa = __half22float2(*reinterpret_cast<__half2*>(&u.x));
        float2 fb = __half22float2(*reinterpret_cast<__half2*>(&u.y));
        acc.x += w * fa.x; acc.y += w * fa.y; acc.z += w * fb.x; acc.w += w * fb.y;
    }
    acc.x += __shfl_xor_sync(0xffffffff, acc.x, 16);
    acc.y += __shfl_xor_sync(0xffffffff, acc.y, 16);
    acc.z += __shfl_xor_sync(0xffffffff, acc.z, 16);
    acc.w += __shfl_xor_sync(0xffffffff, acc.w, 16);
    return acc;
}

// Writes fp32 (exact, for the final mean) and fp16 (for next layer's gathers).
__global__ void k_pull_h(const __half* __restrict__ Hin,
                         float* __restrict__ Fout,
                         __half* __restrict__ Hout) {
    int gwarp = (blockIdx.x * blockDim.x + threadIdx.x) >> 5;
    if (gwarp >= N_NODES) return;
    int lane = threadIdx.x & 31;
    int half = lane >> 4;
    int c    = lane & 15;
    float4 acc = warp_node_reduce_h(Hin, gwarp, c, half);
    if (half == 0) {
        *reinterpret_cast<float4*>(Fout + (size_t)gwarp * D_FEAT + (c << 2)) = acc;
        __half2 h0 = __floats2half2_rn(acc.x, acc.y);
        __half2 h1 = __floats2half2_rn(acc.z, acc.w);
        uint2 u;
        u.x = *reinterpret_cast<unsigned*>(&h0);
        u.y = *reinterpret_cast<unsigned*>(&h1);
        reinterpret_cast<uint2*>(Hout + (size_t)gwarp * D_FEAT)[c] = u;
    }
}

// Final layer fused with the mean: out = 0.25*(X + h1 + h2 + h3)
__global__ void k_pull_final_h(const __half* __restrict__ Hin,   // h2 (fp16)
                               const float* __restrict__ X,
                               const float* __restrict__ h1,
                               const float* __restrict__ h2,
                               float* __restrict__ out) {
    int gwarp = (blockIdx.x * blockDim.x + threadIdx.x) >> 5;
    if (gwarp >= N_NODES) return;
    int lane = threadIdx.x & 31;
    int half = lane >> 4;
    int c    = lane & 15;
    float4 acc = warp_node_reduce_h(Hin, gwarp, c, half);   // h3 chunk
    if (half == 0) {
        size_t idx = (size_t)gwarp * D_FEAT + (c << 2);
        float4 x0 = *reinterpret_cast<const float4*>(X  + idx);
        float4 x1 = *reinterpret_cast<const float4*>(h1 + idx);
        float4 x2 = *reinterpret_cast<const float4*>(h2 + idx);
        float4 o;
        o.x = 0.25f * (x0.x + x1.x + x2.x + acc.x);
        o.y = 0.25f * (x0.y + x1.y + x2.y + acc.y);
        o.z = 0.25f * (x0.z + x1.z + x2.z + acc.z);
        o.w = 0.25f * (x0.w + x1.w + x2.w + acc.w);
        *reinterpret_cast<float4*>(out + idx) = o;
    }
}

extern "C" void kernel_launch(void* const* d_in, const int* in_sizes, int n_in,
                              void* d_out, int out_size) {
    const float* X   = (const float*)d_in[0];
    const int*   src = (const int*)  d_in[1];
    const int*   dst = (const int*)  d_in[2];
    const float* ew  = (const float*)d_in[3];
    float* out = (float*)d_out;

    const int nE = in_sizes[1];

    float* bufA = nullptr;
    float* bufB = nullptr;
    __half* hA = nullptr;
    __half* hB = nullptr;
    cudaGetSymbolAddress((void**)&bufA, g_bufA);
    cudaGetSymbolAddress((void**)&bufB, g_bufB);
    cudaGetSymbolAddress((void**)&hA, g_hA);
    cudaGetSymbolAddress((void**)&hB, g_hB);

    const int TB = 256;
    const int n8       = N_NODES * D_FEAT / 8;
    const int prepN    = (nE > n8) ? nE : n8;
    const int gridPrep = (prepN + TB - 1) / TB;
    const int gridFin  = (N_NODES + 255) / 256;          // 391, 4 per scan chunk
    const int gridE    = (nE + TB - 1) / TB;
    const int gridPull = (N_NODES * 32 + TB - 1) / TB;   // warp per node

    // --- build dst-sorted CSR (deg starts zeroed: static init / previous call) ---
    k_prep<<<gridPrep, TB>>>(X, hA, dst, n8, nE);        // x2h + hist
    k_scan_block<<<N_SCAN_BLOCKS, SCAN_BS>>>(N_NODES);   // local scan + deg reset
    k_finalize<<<gridFin, 256>>>(N_NODES, nE);           // off + cursor
    k_scatter<<<gridE, TB>>>(src, dst, ew, nE);          // packed (src, ew)

    // --- 3 pull layers (fp16 gathers, fp32 accumulation + mean) ---
    k_pull_h<<<gridPull, TB>>>(hA, bufA, hB);                    // h1
    k_pull_h<<<gridPull, TB>>>(hB, bufB, hA);                    // h2
    k_pull_final_h<<<gridPull, TB>>>(hA, X, bufA, bufB, out);    // h3 + mean
}

// round 7
// speedup vs baseline: 1.5121x; 1.0043x over previous
#include <cuda_runtime.h>
#include <cuda_fp16.h>
#include <cstdint>

// LightGCN: out = 0.25*(X + h1 + h2 + h3), h_{k+1} = A h_k
// Pull-based CSR, fp16 gather operands / fp32 accumulation.
// R7: atomic-free scatter — the histogram's atomicAdd return value doubles as
// each edge's within-destination rank, so placement is off[dst]+rank.

#define N_NODES 100000
#define D_FEAT  64
#define MAX_E   1600000
#define SCAN_BS 1024
#define N_SCAN_BLOCKS ((N_NODES + SCAN_BS - 1) / SCAN_BS)   // 98

// Static scratch (no allocation allowed). deg is self-restoring: consumed and
// re-zeroed inside k_scan_block each call (static zero-init covers call #1).
__device__ float  g_bufA[(size_t)N_NODES * D_FEAT];   // h1 (fp32, exact for mean)
__device__ float  g_bufB[(size_t)N_NODES * D_FEAT];   // h2 (fp32, exact for mean)
__device__ __half g_hA[(size_t)N_NODES * D_FEAT];     // fp16 gather copies
__device__ __half g_hB[(size_t)N_NODES * D_FEAT];
__device__ int    g_deg[N_NODES];
__device__ int    g_exloc[N_NODES];                   // block-local exclusive prefix
__device__ int    g_blockSums[N_SCAN_BLOCKS];
__device__ int    g_off[N_NODES + 1];
__device__ int    g_rank[MAX_E];                      // edge rank within its dst
__device__ int2   g_sedge[MAX_E];                     // packed (src, ew), dst-sorted

// ---- prep: fp32->fp16 convert of X, fused with the dst histogram.
//      The atomic's old value IS the edge's rank within its destination. ----
__global__ void k_prep(const float* __restrict__ X, __half* __restrict__ hX,
                       const int* __restrict__ dst, int n8, int nE) {
    int i = blockIdx.x * blockDim.x + threadIdx.x;
    if (i < n8) {
        const float4* x4 = reinterpret_cast<const float4*>(X);
        float4 a = x4[2 * i];
        float4 b = x4[2 * i + 1];
        __half2 h0 = __floats2half2_rn(a.x, a.y);
        __half2 h1 = __floats2half2_rn(a.z, a.w);
        __half2 h2 = __floats2half2_rn(b.x, b.y);
        __half2 h3 = __floats2half2_rn(b.z, b.w);
        uint4 r;
        r.x = *reinterpret_cast<unsigned*>(&h0);
        r.y = *reinterpret_cast<unsigned*>(&h1);
        r.z = *reinterpret_cast<unsigned*>(&h2);
        r.w = *reinterpret_cast<unsigned*>(&h3);
        reinterpret_cast<uint4*>(hX)[i] = r;
    }
    if (i < nE) g_rank[i] = atomicAdd(&g_deg[dst[i]], 1);
}

// ---- per-block scan: block-local EXCLUSIVE prefix + block sums; resets deg ----
__global__ void k_scan_block(int n) {
    __shared__ int sh[SCAN_BS];
    int t = threadIdx.x;
    int i = blockIdx.x * SCAN_BS + t;
    int v = (i < n) ? g_deg[i] : 0;
    sh[t] = v;
    __syncthreads();
    for (int d = 1; d < SCAN_BS; d <<= 1) {
        int x = (t >= d) ? sh[t - d] : 0;
        __syncthreads();
        sh[t] += x;
        __syncthreads();
    }
    if (i < n) {
        g_exloc[i] = sh[t] - v;   // exclusive within block
        g_deg[i] = 0;             // self-restore for next replay
    }
    if (t == SCAN_BS - 1) g_blockSums[blockIdx.x] = sh[t];
}

// ---- finalize: each 256-thread block recomputes its chunk's global base
//      from the 98 block sums (L2-hot), writes off ----
__global__ void k_finalize(int n, int nE) {
    __shared__ int s_base;
    int chunk = blockIdx.x >> 2;   // 4 blocks of 256 per 1024-wide scan chunk
    if (threadIdx.x < 32) {
        int acc = 0;
        for (int j = (int)threadIdx.x; j < chunk; j += 32) acc += g_blockSums[j];
        #pragma unroll
        for (int o = 16; o; o >>= 1) acc += __shfl_down_sync(0xffffffffu, acc, o);
        if (threadIdx.x == 0) s_base = acc;
    }
    __syncthreads();
    int i = blockIdx.x * 256 + threadIdx.x;
    if (i >= n) return;
    g_off[i] = g_exloc[i] + s_base;
    if (i == n - 1) g_off[n] = nE;
}

// ---- scatter: pure streaming, NO atomics ----
__global__ void k_scatter(const int* __restrict__ src,
                          const int* __restrict__ dst,
                          const float* __restrict__ ew, int nE) {
    int e = blockIdx.x * blockDim.x + threadIdx.x;
    if (e >= nE) return;
    int pos = g_off[dst[e]] + g_rank[e];
    g_sedge[pos] = make_int2(src[e], __float_as_int(ew[e]));
}

// ---------------- Pull SpMM (fp16 gathers, fp32 accumulate) ----------------
// One warp per dst node. Lanes 0-15 = even edges, lanes 16-31 = odd edges.
// Lane c (0..15) owns features [4c, 4c+4): 16 lanes x 8B = the full 128B row.

__device__ __forceinline__ float4 warp_node_reduce_h(const __half* __restrict__ Hin,
                                                     int node, int c, int half) {
    int begin = g_off[node], end = g_off[node + 1];
    float4 acc = make_float4(0.f, 0.f, 0.f, 0.f);
    for (int e = begin + half; e < end; e += 2) {
        int2  p = g_sedge[e];
        float w = __int_as_float(p.y);
        uint2 u = reinterpret_cast<const uint2*>(Hin + (size_t)p.x * D_FEAT)[c];
        float2 fa = __half22float2(*reinterpret_cast<__half2*>(&u.x));
        float2 fb = __half22float2(*reinterpret_cast<__half2*>(&u.y));
        acc.x += w * fa.x; acc.y += w * fa.y; acc.z += w * fb.x; acc.w += w * fb.y;
    }
    acc.x += __shfl_xor_sync(0xffffffff, acc.x, 16);
    acc.y += __shfl_xor_sync(0xffffffff, acc.y, 16);
    acc.z += __shfl_xor_sync(0xffffffff, acc.z, 16);
    acc.w += __shfl_xor_sync(0xffffffff, acc.w, 16);
    return acc;
}

// Writes fp32 (exact, for the final mean) and fp16 (for next layer's gathers).
__global__ void k_pull_h(const __half* __restrict__ Hin,
                         float* __restrict__ Fout,
                         __half* __restrict__ Hout) {
    int gwarp = (blockIdx.x * blockDim.x + threadIdx.x) >> 5;
    if (gwarp >= N_NODES) return;
    int lane = threadIdx.x & 31;
    int half = lane >> 4;
    int c    = lane & 15;
    float4 acc = warp_node_reduce_h(Hin, gwarp, c, half);
    if (half == 0) {
        *reinterpret_cast<float4*>(Fout + (size_t)gwarp * D_FEAT + (c << 2)) = acc;
        __half2 h0 = __floats2half2_rn(acc.x, acc.y);
        __half2 h1 = __floats2half2_rn(acc.z, acc.w);
        uint2 u;
        u.x = *reinterpret_cast<unsigned*>(&h0);
        u.y = *reinterpret_cast<unsigned*>(&h1);
        reinterpret_cast<uint2*>(Hout + (size_t)gwarp * D_FEAT)[c] = u;
    }
}

// Final layer fused with the mean: out = 0.25*(X + h1 + h2 + h3)
__global__ void k_pull_final_h(const __half* __restrict__ Hin,   // h2 (fp16)
                               const float* __restrict__ X,
                               const float* __restrict__ h1,
                               const float* __restrict__ h2,
                               float* __restrict__ out) {
    int gwarp = (blockIdx.x * blockDim.x + threadIdx.x) >> 5;
    if (gwarp >= N_NODES) return;
    int lane = threadIdx.x & 31;
    int half = lane >> 4;
    int c    = lane & 15;
    float4 acc = warp_node_reduce_h(Hin, gwarp, c, half);   // h3 chunk
    if (half == 0) {
        size_t idx = (size_t)gwarp * D_FEAT + (c << 2);
        float4 x0 = *reinterpret_cast<const float4*>(X  + idx);
        float4 x1 = *reinterpret_cast<const float4*>(h1 + idx);
        float4 x2 = *reinterpret_cast<const float4*>(h2 + idx);
        float4 o;
        o.x = 0.25f * (x0.x + x1.x + x2.x + acc.x);
        o.y = 0.25f * (x0.y + x1.y + x2.y + acc.y);
        o.z = 0.25f * (x0.z + x1.z + x2.z + acc.z);
        o.w = 0.25f * (x0.w + x1.w + x2.w + acc.w);
        *reinterpret_cast<float4*>(out + idx) = o;
    }
}

extern "C" void kernel_launch(void* const* d_in, const int* in_sizes, int n_in,
                              void* d_out, int out_size) {
    const float* X   = (const float*)d_in[0];
    const int*   src = (const int*)  d_in[1];
    const int*   dst = (const int*)  d_in[2];
    const float* ew  = (const float*)d_in[3];
    float* out = (float*)d_out;

    const int nE = in_sizes[1];

    float* bufA = nullptr;
    float* bufB = nullptr;
    __half* hA = nullptr;
    __half* hB = nullptr;
    cudaGetSymbolAddress((void**)&bufA, g_bufA);
    cudaGetSymbolAddress((void**)&bufB, g_bufB);
    cudaGetSymbolAddress((void**)&hA, g_hA);
    cudaGetSymbolAddress((void**)&hB, g_hB);

    const int TB = 256;
    const int n8       = N_NODES * D_FEAT / 8;
    const int prepN    = (nE > n8) ? nE : n8;
    const int gridPrep = (prepN + TB - 1) / TB;
    const int gridFin  = (N_NODES + 255) / 256;          // 391, 4 per scan chunk
    const int gridE    = (nE + TB - 1) / TB;
    const int gridPull = (N_NODES * 32 + TB - 1) / TB;   // warp per node

    // --- build dst-sorted CSR ---
    k_prep<<<gridPrep, TB>>>(X, hA, dst, n8, nE);        // x2h + hist + ranks
    k_scan_block<<<N_SCAN_BLOCKS, SCAN_BS>>>(N_NODES);   // local scan + deg reset
    k_finalize<<<gridFin, 256>>>(N_NODES, nE);           // off
    k_scatter<<<gridE, TB>>>(src, dst, ew, nE);          // atomic-free placement

    // --- 3 pull layers (fp16 gathers, fp32 accumulation + mean) ---
    k_pull_h<<<gridPull, TB>>>(hA, bufA, hB);                    // h1
    k_pull_h<<<gridPull, TB>>>(hB, bufB, hA);                    // h2
    k_pull_final_h<<<gridPull, TB>>>(hA, X, bufA, bufB, out);    // h3 + mean
}

// round 8
// speedup vs baseline: 1.5759x; 1.0422x over previous
#include <cuda_runtime.h>
#include <cuda_fp16.h>
#include <cstdint>

// LightGCN: out = 0.25*(X + h1 + h2 + h3), h_{k+1} = A h_k
// Pull-based CSR, fp16 gather operands / fp32 accumulation.
// R8: fp16-only intermediates (h3's magnitude dominates the mean, so fp16
// rounding of the h1/h2 mean terms is negligible); bufA/bufB removed.

#define N_NODES 100000
#define D_FEAT  64
#define MAX_E   1600000
#define SCAN_BS 1024
#define N_SCAN_BLOCKS ((N_NODES + SCAN_BS - 1) / SCAN_BS)   // 98

// Static scratch (no allocation allowed). deg is self-restoring: consumed and
// re-zeroed inside k_scan_block each call (static zero-init covers call #1).
__device__ __half g_hX[(size_t)N_NODES * D_FEAT];     // X in fp16
__device__ __half g_h1[(size_t)N_NODES * D_FEAT];     // h1 in fp16
__device__ __half g_h2[(size_t)N_NODES * D_FEAT];     // h2 in fp16
__device__ int    g_deg[N_NODES];
__device__ int    g_exloc[N_NODES];                   // block-local exclusive prefix
__device__ int    g_blockSums[N_SCAN_BLOCKS];
__device__ int    g_off[N_NODES + 1];
__device__ int    g_rank[MAX_E];                      // edge rank within its dst
__device__ int2   g_sedge[MAX_E];                     // packed (src, ew), dst-sorted

// ---- prep: fp32->fp16 convert of X, fused with the dst histogram.
//      The atomic's old value IS the edge's rank within its destination. ----
__global__ void k_prep(const float* __restrict__ X, __half* __restrict__ hX,
                       const int* __restrict__ dst, int n8, int nE) {
    int i = blockIdx.x * blockDim.x + threadIdx.x;
    if (i < n8) {
        const float4* x4 = reinterpret_cast<const float4*>(X);
        float4 a = x4[2 * i];
        float4 b = x4[2 * i + 1];
        __half2 h0 = __floats2half2_rn(a.x, a.y);
        __half2 h1 = __floats2half2_rn(a.z, a.w);
        __half2 h2 = __floats2half2_rn(b.x, b.y);
        __half2 h3 = __floats2half2_rn(b.z, b.w);
        uint4 r;
        r.x = *reinterpret_cast<unsigned*>(&h0);
        r.y = *reinterpret_cast<unsigned*>(&h1);
        r.z = *reinterpret_cast<unsigned*>(&h2);
        r.w = *reinterpret_cast<unsigned*>(&h3);
        reinterpret_cast<uint4*>(hX)[i] = r;
    }
    if (i < nE) g_rank[i] = atomicAdd(&g_deg[dst[i]], 1);
}

// ---- per-block scan: block-local EXCLUSIVE prefix + block sums; resets deg ----
__global__ void k_scan_block(int n) {
    __shared__ int sh[SCAN_BS];
    int t = threadIdx.x;
    int i = blockIdx.x * SCAN_BS + t;
    int v = (i < n) ? g_deg[i] : 0;
    sh[t] = v;
    __syncthreads();
    for (int d = 1; d < SCAN_BS; d <<= 1) {
        int x = (t >= d) ? sh[t - d] : 0;
        __syncthreads();
        sh[t] += x;
        __syncthreads();
    }
    if (i < n) {
        g_exloc[i] = sh[t] - v;   // exclusive within block
        g_deg[i] = 0;             // self-restore for next replay
    }
    if (t == SCAN_BS - 1) g_blockSums[blockIdx.x] = sh[t];
}

// ---- finalize: each 256-thread block recomputes its chunk's global base
//      from the 98 block sums (L2-hot), writes off ----
__global__ void k_finalize(int n, int nE) {
    __shared__ int s_base;
    int chunk = blockIdx.x >> 2;   // 4 blocks of 256 per 1024-wide scan chunk
    if (threadIdx.x < 32) {
        int acc = 0;
        for (int j = (int)threadIdx.x; j < chunk; j += 32) acc += g_blockSums[j];
        #pragma unroll
        for (int o = 16; o; o >>= 1) acc += __shfl_down_sync(0xffffffffu, acc, o);
        if (threadIdx.x == 0) s_base = acc;
    }
    __syncthreads();
    int i = blockIdx.x * 256 + threadIdx.x;
    if (i >= n) return;
    g_off[i] = g_exloc[i] + s_base;
    if (i == n - 1) g_off[n] = nE;
}

// ---- scatter: pure streaming, NO atomics ----
__global__ void k_scatter(const int* __restrict__ src,
                          const int* __restrict__ dst,
                          const float* __restrict__ ew, int nE) {
    int e = blockIdx.x * blockDim.x + threadIdx.x;
    if (e >= nE) return;
    int pos = g_off[dst[e]] + g_rank[e];
    g_sedge[pos] = make_int2(src[e], __float_as_int(ew[e]));
}

// ---------------- Pull SpMM (fp16 gathers, fp32 accumulate) ----------------
// One warp per dst node. Lanes 0-15 = even edges, lanes 16-31 = odd edges.
// Lane c (0..15) owns features [4c, 4c+4): 16 lanes x 8B = the full 128B row.

__device__ __forceinline__ float4 warp_node_reduce_h(const __half* __restrict__ Hin,
                                                     int node, int c, int half) {
    int begin = g_off[node], end = g_off[node + 1];
    float4 acc = make_float4(0.f, 0.f, 0.f, 0.f);
    for (int e = begin + half; e < end; e += 2) {
        int2  p = g_sedge[e];
        float w = __int_as_float(p.y);
        uint2 u = reinterpret_cast<const uint2*>(Hin + (size_t)p.x * D_FEAT)[c];
        float2 fa = __half22float2(*reinterpret_cast<__half2*>(&u.x));
        float2 fb = __half22float2(*reinterpret_cast<__half2*>(&u.y));
        acc.x += w * fa.x; acc.y += w * fa.y; acc.z += w * fb.x; acc.w += w * fb.y;
    }
    acc.x += __shfl_xor_sync(0xffffffff, acc.x, 16);
    acc.y += __shfl_xor_sync(0xffffffff, acc.y, 16);
    acc.z += __shfl_xor_sync(0xffffffff, acc.z, 16);
    acc.w += __shfl_xor_sync(0xffffffff, acc.w, 16);
    return acc;
}

// Intermediate layer: write fp16 only.
__global__ void k_pull_h(const __half* __restrict__ Hin,
                         __half* __restrict__ Hout) {
    int gwarp = (blockIdx.x * blockDim.x + threadIdx.x) >> 5;
    if (gwarp >= N_NODES) return;
    int lane = threadIdx.x & 31;
    int half = lane >> 4;
    int c    = lane & 15;
    float4 acc = warp_node_reduce_h(Hin, gwarp, c, half);
    if (half == 0) {
        __half2 h0 = __floats2half2_rn(acc.x, acc.y);
        __half2 h1 = __floats2half2_rn(acc.z, acc.w);
        uint2 u;
        u.x = *reinterpret_cast<unsigned*>(&h0);
        u.y = *reinterpret_cast<unsigned*>(&h1);
        reinterpret_cast<uint2*>(Hout + (size_t)gwarp * D_FEAT)[c] = u;
    }
}

// Final layer fused with the mean: out = 0.25*(X + h1 + h2 + h3).
// X is fp32 (exact); h1, h2 read as fp16 (their mean contribution is 8-64x
// smaller than h3's, so the rounding is negligible); h3 = fresh fp32 reduce.
__global__ void k_pull_final_h(const __half* __restrict__ Hin,   // h2 (fp16)
                               const float* __restrict__ X,
                               const __half* __restrict__ H1,
                               float* __restrict__ out) {
    int gwarp = (blockIdx.x * blockDim.x + threadIdx.x) >> 5;
    if (gwarp >= N_NODES) return;
    int lane = threadIdx.x & 31;
    int half = lane >> 4;
    int c    = lane & 15;
    float4 acc = warp_node_reduce_h(Hin, gwarp, c, half);   // h3 chunk
    if (half == 0) {
        size_t idx = (size_t)gwarp * D_FEAT + (c << 2);
        float4 x0 = *reinterpret_cast<const float4*>(X + idx);
        uint2 u1 = reinterpret_cast<const uint2*>(H1  + (size_t)gwarp * D_FEAT)[c];
        uint2 u2 = reinterpret_cast<const uint2*>(Hin + (size_t)gwarp * D_FEAT)[c];
        float2 a1 = __half22float2(*reinterpret_cast<__half2*>(&u1.x));
        float2 b1 = __half22float2(*reinterpret_cast<__half2*>(&u1.y));
        float2 a2 = __half22float2(*reinterpret_cast<__half2*>(&u2.x));
        float2 b2 = __half22float2(*reinterpret_cast<__half2*>(&u2.y));
        float4 o;
        o.x = 0.25f * (x0.x + a1.x + a2.x + acc.x);
        o.y = 0.25f * (x0.y + a1.y + a2.y + acc.y);
        o.z = 0.25f * (x0.z + b1.x + b2.x + acc.z);
        o.w = 0.25f * (x0.w + b1.y + b2.y + acc.w);
        *reinterpret_cast<float4*>(out + idx) = o;
    }
}

extern "C" void kernel_launch(void* const* d_in, const int* in_sizes, int n_in,
                              void* d_out, int out_size) {
    const float* X   = (const float*)d_in[0];
    const int*   src = (const int*)  d_in[1];
    const int*   dst = (const int*)  d_in[2];
    const float* ew  = (const float*)d_in[3];
    float* out = (float*)d_out;

    const int nE = in_sizes[1];

    __half* hX = nullptr;
    __half* h1 = nullptr;
    __half* h2 = nullptr;
    cudaGetSymbolAddress((void**)&hX, g_hX);
    cudaGetSymbolAddress((void**)&h1, g_h1);
    cudaGetSymbolAddress((void**)&h2, g_h2);

    const int TB = 256;
    const int n8       = N_NODES * D_FEAT / 8;
    const int prepN    = (nE > n8) ? nE : n8;
    const int gridPrep = (prepN + TB - 1) / TB;
    const int gridFin  = (N_NODES + 255) / 256;          // 391, 4 per scan chunk
    const int gridE    = (nE + TB - 1) / TB;
    const int gridPull = (N_NODES * 32 + TB - 1) / TB;   // warp per node

    // --- build dst-sorted CSR ---
    k_prep<<<gridPrep, TB>>>(X, hX, dst, n8, nE);        // x2h + hist + ranks
    k_scan_block<<<N_SCAN_BLOCKS, SCAN_BS>>>(N_NODES);   // local scan + deg reset
    k_finalize<<<gridFin, 256>>>(N_NODES, nE);           // off
    k_scatter<<<gridE, TB>>>(src, dst, ew, nE);          // atomic-free placement

    // --- 3 pull layers (fp16 gathers/intermediates, fp32 accumulation + mean) ---
    k_pull_h<<<gridPull, TB>>>(hX, h1);                  // h1
    k_pull_h<<<gridPull, TB>>>(h1, h2);                  // h2
    k_pull_final_h<<<gridPull, TB>>>(h2, X, h1, out);    // h3 + mean
}